// round 1
// baseline (speedup 1.0000x reference)
#include <cuda_runtime.h>
#include <math.h>

#define SLEN  2048
#define EMB   2048
#define DFF   8192
#define NHEAD 16
#define HDIM  128
#define WIN   512
#define LNEPS 1e-5f

// ---------------- scratch (no allocations allowed) ----------------
__device__ float g_xn [SLEN*EMB];
__device__ float g_q  [SLEN*EMB];
__device__ float g_k  [SLEN*EMB];
__device__ float g_v  [SLEN*EMB];
__device__ float g_ctx[SLEN*EMB];
__device__ float g_x1 [SLEN*EMB];
__device__ float g_x2 [SLEN*EMB];
__device__ float g_h  [SLEN*DFF];

// ---------------- layernorm: one block per row ----------------
__global__ void ln_kernel(const float* __restrict__ x, const float* __restrict__ gam,
                          const float* __restrict__ bet, float* __restrict__ y)
{
    int row = blockIdx.x;
    const float* xr = x + (size_t)row * EMB;
    float vals[8];
    float s = 0.f, ss = 0.f;
#pragma unroll
    for (int i = 0; i < 8; i++) {
        float v = xr[threadIdx.x + i * 256];
        vals[i] = v; s += v; ss += v * v;
    }
#pragma unroll
    for (int o = 16; o; o >>= 1) {
        s  += __shfl_xor_sync(~0u, s,  o);
        ss += __shfl_xor_sync(~0u, ss, o);
    }
    __shared__ float rs[8], rss[8];
    int warp = threadIdx.x >> 5, lane = threadIdx.x & 31;
    if (lane == 0) { rs[warp] = s; rss[warp] = ss; }
    __syncthreads();
    if (warp == 0) {
        float a  = (lane < 8) ? rs[lane]  : 0.f;
        float b2 = (lane < 8) ? rss[lane] : 0.f;
#pragma unroll
        for (int o = 4; o; o >>= 1) {
            a  += __shfl_xor_sync(~0u, a,  o);
            b2 += __shfl_xor_sync(~0u, b2, o);
        }
        if (lane == 0) { rs[0] = a; rss[0] = b2; }
    }
    __syncthreads();
    float mean = rs[0]  * (1.f / EMB);
    float var  = rss[0] * (1.f / EMB) - mean * mean;
    float inv  = rsqrtf(var + LNEPS);
    float* yr = y + (size_t)row * EMB;
#pragma unroll
    for (int i = 0; i < 8; i++) {
        int c = threadIdx.x + i * 256;
        yr[c] = (vals[i] - mean) * inv * gam[c] + bet[c];
    }
}

// ---------------- generic fp32 GEMM, 128x128x16 tiles ----------------
// EPI: 0 = +bias, 1 = +bias+residual, 2 = +bias then exact GELU
__device__ __forceinline__ float gelu_exact(float v) {
    return 0.5f * v * (1.0f + erff(v * 0.70710678118654752440f));
}

template<int EPI>
__global__ __launch_bounds__(256, 2) void gemm_kernel(
    const float* __restrict__ A, const float* __restrict__ B,
    const float* __restrict__ bias, const float* __restrict__ res,
    float* __restrict__ C, int M, int N, int K)
{
    __shared__ float As[2][16][128];   // As[k][m] (A transposed)
    __shared__ float Bs[2][16][128];   // Bs[k][n]

    const int tid = threadIdx.x;
    const int tx = tid & 15, ty = tid >> 4;
    const int m0 = blockIdx.y * 128, n0 = blockIdx.x * 128;
    const int ar = tid >> 1, ac = (tid & 1) * 8;   // A tile loader coords
    const int br = tid >> 4, bc = (tid & 15) * 8;  // B tile loader coords

    const float* Ap = A + (size_t)(m0 + ar) * K + ac;
    const float* Bp = B + (size_t)br * N + n0 + bc;

    float ra[8], rb[8];
    {
        float4 a0 = *(const float4*)(Ap);
        float4 a1 = *(const float4*)(Ap + 4);
        float4 b0 = *(const float4*)(Bp);
        float4 b1 = *(const float4*)(Bp + 4);
        ra[0]=a0.x; ra[1]=a0.y; ra[2]=a0.z; ra[3]=a0.w;
        ra[4]=a1.x; ra[5]=a1.y; ra[6]=a1.z; ra[7]=a1.w;
        rb[0]=b0.x; rb[1]=b0.y; rb[2]=b0.z; rb[3]=b0.w;
        rb[4]=b1.x; rb[5]=b1.y; rb[6]=b1.z; rb[7]=b1.w;
    }
#pragma unroll
    for (int j = 0; j < 8; j++) As[0][ac + j][ar] = ra[j];
    *(float4*)&Bs[0][br][bc]     = make_float4(rb[0], rb[1], rb[2], rb[3]);
    *(float4*)&Bs[0][br][bc + 4] = make_float4(rb[4], rb[5], rb[6], rb[7]);
    __syncthreads();

    float acc[8][8];
#pragma unroll
    for (int i = 0; i < 8; i++)
#pragma unroll
        for (int j = 0; j < 8; j++) acc[i][j] = 0.f;

    const int KT = K >> 4;
    for (int kt = 0; kt < KT; kt++) {
        const int cur = kt & 1;
        if (kt + 1 < KT) {
            const float* Ap2 = Ap + (size_t)(kt + 1) * 16;
            const float* Bp2 = Bp + (size_t)(kt + 1) * 16 * N;
            float4 a0 = *(const float4*)(Ap2);
            float4 a1 = *(const float4*)(Ap2 + 4);
            float4 b0 = *(const float4*)(Bp2);
            float4 b1 = *(const float4*)(Bp2 + 4);
            ra[0]=a0.x; ra[1]=a0.y; ra[2]=a0.z; ra[3]=a0.w;
            ra[4]=a1.x; ra[5]=a1.y; ra[6]=a1.z; ra[7]=a1.w;
            rb[0]=b0.x; rb[1]=b0.y; rb[2]=b0.z; rb[3]=b0.w;
            rb[4]=b1.x; rb[5]=b1.y; rb[6]=b1.z; rb[7]=b1.w;
        }
#pragma unroll
        for (int kk = 0; kk < 16; kk++) {
            float4 a0 = *(const float4*)&As[cur][kk][ty * 8];
            float4 a1 = *(const float4*)&As[cur][kk][ty * 8 + 4];
            float4 b0 = *(const float4*)&Bs[cur][kk][tx * 8];
            float4 b1 = *(const float4*)&Bs[cur][kk][tx * 8 + 4];
            float av[8] = {a0.x, a0.y, a0.z, a0.w, a1.x, a1.y, a1.z, a1.w};
            float bv[8] = {b0.x, b0.y, b0.z, b0.w, b1.x, b1.y, b1.z, b1.w};
#pragma unroll
            for (int i = 0; i < 8; i++)
#pragma unroll
                for (int j = 0; j < 8; j++)
                    acc[i][j] = fmaf(av[i], bv[j], acc[i][j]);
        }
        if (kt + 1 < KT) {
            const int nxt = cur ^ 1;
#pragma unroll
            for (int j = 0; j < 8; j++) As[nxt][ac + j][ar] = ra[j];
            *(float4*)&Bs[nxt][br][bc]     = make_float4(rb[0], rb[1], rb[2], rb[3]);
            *(float4*)&Bs[nxt][br][bc + 4] = make_float4(rb[4], rb[5], rb[6], rb[7]);
            __syncthreads();
        }
    }

    const int row = m0 + ty * 8, col = n0 + tx * 8;
#pragma unroll
    for (int i = 0; i < 8; i++) {
        float out[8];
#pragma unroll
        for (int j = 0; j < 8; j++) {
            float vv = acc[i][j] + bias[col + j];
            if (EPI == 1) vv += res[(size_t)(row + i) * N + col + j];
            if (EPI == 2) vv = gelu_exact(vv);
            out[j] = vv;
        }
        *(float4*)&C[(size_t)(row + i) * N + col]     = make_float4(out[0], out[1], out[2], out[3]);
        *(float4*)&C[(size_t)(row + i) * N + col + 4] = make_float4(out[4], out[5], out[6], out[7]);
    }
}

// ---------------- fused sliding-window attention ----------------
// grid: (S/64, NHEAD), block 256. Flash-style online softmax.
#define QT_STR 68
#define VS_STR 132
#define PS_STR 65
#define ATTN_SMEM ((128*QT_STR*2 + 64*VS_STR + 64*PS_STR) * 4)
#define QK_SCALE 0.08838834764831845f   // 1/sqrt(128)

__global__ __launch_bounds__(256) void attn_kernel(
    const float* __restrict__ q, const float* __restrict__ k,
    const float* __restrict__ v, float* __restrict__ ctx)
{
    extern __shared__ float sm[];
    float* Qt = sm;                    // [128][QT_STR] d-major (pre-scaled)
    float* Kt = Qt + 128 * QT_STR;     // [128][QT_STR] d-major
    float* Vs = Kt + 128 * QT_STR;     // [64][VS_STR]  key-major
    float* Ps = Vs + 64 * VS_STR;      // [64][PS_STR]

    const int h = blockIdx.y, qt = blockIdx.x;
    const int q0 = qt * 64;
    const int tid  = threadIdx.x;
    const int warp = tid >> 5, lane = tid & 31;
    const int tr = tid >> 4, tc = tid & 15;   // 16x16 thread grid, 4x4 S tiles

    // load Q tile transposed, fold in 1/sqrt(hd)
#pragma unroll
    for (int rr = 0; rr < 8; rr++) {
        int r = warp * 8 + rr;
        float4 qv = *(const float4*)&q[(size_t)(q0 + r) * EMB + h * HDIM + lane * 4];
        Qt[(lane * 4 + 0) * QT_STR + r] = qv.x * QK_SCALE;
        Qt[(lane * 4 + 1) * QT_STR + r] = qv.y * QK_SCALE;
        Qt[(lane * 4 + 2) * QT_STR + r] = qv.z * QK_SCALE;
        Qt[(lane * 4 + 3) * QT_STR + r] = qv.w * QK_SCALE;
    }

    float m_i[4], l_i[4], o[4][8];
#pragma unroll
    for (int ii = 0; ii < 4; ii++) {
        m_i[ii] = -1e30f; l_i[ii] = 0.f;
#pragma unroll
        for (int dd = 0; dd < 8; dd++) o[ii][dd] = 0.f;
    }

    const int kt0 = (q0 > WIN) ? ((q0 - WIN) >> 6) : 0;
    for (int kt = kt0; kt <= qt; kt++) {
        const int j0 = kt * 64;
        __syncthreads();   // previous-iteration smem fully consumed
#pragma unroll
        for (int rr = 0; rr < 8; rr++) {
            int r = warp * 8 + rr;
            float4 kv = *(const float4*)&k[(size_t)(j0 + r) * EMB + h * HDIM + lane * 4];
            Kt[(lane * 4 + 0) * QT_STR + r] = kv.x;
            Kt[(lane * 4 + 1) * QT_STR + r] = kv.y;
            Kt[(lane * 4 + 2) * QT_STR + r] = kv.z;
            Kt[(lane * 4 + 3) * QT_STR + r] = kv.w;
            float4 vv = *(const float4*)&v[(size_t)(j0 + r) * EMB + h * HDIM + lane * 4];
            *(float4*)&Vs[r * VS_STR + lane * 4] = vv;
        }
        __syncthreads();

        // S = Q K^T  (4x4 per thread)
        float sacc[4][4];
#pragma unroll
        for (int ii = 0; ii < 4; ii++)
#pragma unroll
            for (int jj = 0; jj < 4; jj++) sacc[ii][jj] = 0.f;
#pragma unroll 8
        for (int d = 0; d < 128; d++) {
            float4 a = *(const float4*)&Qt[d * QT_STR + tr * 4];
            float4 b = *(const float4*)&Kt[d * QT_STR + tc * 4];
            float av[4] = {a.x, a.y, a.z, a.w};
            float bv[4] = {b.x, b.y, b.z, b.w};
#pragma unroll
            for (int ii = 0; ii < 4; ii++)
#pragma unroll
                for (int jj = 0; jj < 4; jj++)
                    sacc[ii][jj] = fmaf(av[ii], bv[jj], sacc[ii][jj]);
        }

        // masked online softmax (rows shared by 16 tc-lanes within half-warp)
#pragma unroll
        for (int ii = 0; ii < 4; ii++) {
            const int i = q0 + tr * 4 + ii;
            bool bn[4];
            float rmax = -1e30f;
#pragma unroll
            for (int jj = 0; jj < 4; jj++) {
                int j = j0 + tc * 4 + jj;
                bn[jj] = (j > i) || (i - j > WIN);
                float val = bn[jj] ? -1e30f : sacc[ii][jj];
                sacc[ii][jj] = val;
                rmax = fmaxf(rmax, val);
            }
#pragma unroll
            for (int off = 8; off; off >>= 1)
                rmax = fmaxf(rmax, __shfl_xor_sync(~0u, rmax, off));
            float mnew  = fmaxf(m_i[ii], rmax);
            float alpha = __expf(m_i[ii] - mnew);
            float rsum = 0.f;
#pragma unroll
            for (int jj = 0; jj < 4; jj++) {
                float p = bn[jj] ? 0.f : __expf(sacc[ii][jj] - mnew);
                Ps[(tr * 4 + ii) * PS_STR + tc * 4 + jj] = p;
                rsum += p;
            }
#pragma unroll
            for (int off = 8; off; off >>= 1)
                rsum += __shfl_xor_sync(~0u, rsum, off);
            l_i[ii] = l_i[ii] * alpha + rsum;
            m_i[ii] = mnew;
#pragma unroll
            for (int dd = 0; dd < 8; dd++) o[ii][dd] *= alpha;
        }
        __syncthreads();   // Ps complete

        // O += P V   (4 rows x 8 dims per thread)
#pragma unroll 8
        for (int kk = 0; kk < 64; kk++) {
            float4 v0 = *(const float4*)&Vs[kk * VS_STR + tc * 8];
            float4 v1 = *(const float4*)&Vs[kk * VS_STR + tc * 8 + 4];
#pragma unroll
            for (int ii = 0; ii < 4; ii++) {
                float p = Ps[(tr * 4 + ii) * PS_STR + kk];
                o[ii][0] = fmaf(p, v0.x, o[ii][0]);
                o[ii][1] = fmaf(p, v0.y, o[ii][1]);
                o[ii][2] = fmaf(p, v0.z, o[ii][2]);
                o[ii][3] = fmaf(p, v0.w, o[ii][3]);
                o[ii][4] = fmaf(p, v1.x, o[ii][4]);
                o[ii][5] = fmaf(p, v1.y, o[ii][5]);
                o[ii][6] = fmaf(p, v1.z, o[ii][6]);
                o[ii][7] = fmaf(p, v1.w, o[ii][7]);
            }
        }
    }

#pragma unroll
    for (int ii = 0; ii < 4; ii++) {
        float inv = 1.f / l_i[ii];
        size_t base = (size_t)(q0 + tr * 4 + ii) * EMB + h * HDIM + tc * 8;
        *(float4*)&ctx[base]     = make_float4(o[ii][0]*inv, o[ii][1]*inv, o[ii][2]*inv, o[ii][3]*inv);
        *(float4*)&ctx[base + 4] = make_float4(o[ii][4]*inv, o[ii][5]*inv, o[ii][6]*inv, o[ii][7]*inv);
    }
}

// ---------------- launch ----------------
extern "C" void kernel_launch(void* const* d_in, const int* in_sizes, int n_in,
                              void* d_out, int out_size)
{
    const float* x    = (const float*)d_in[0];
    const float* Wq   = (const float*)d_in[1];
    const float* bq   = (const float*)d_in[2];
    const float* Wk   = (const float*)d_in[3];
    const float* bk   = (const float*)d_in[4];
    const float* Wv   = (const float*)d_in[5];
    const float* bv   = (const float*)d_in[6];
    const float* Wo   = (const float*)d_in[7];
    const float* bo   = (const float*)d_in[8];
    const float* ln1g = (const float*)d_in[9];
    const float* ln1b = (const float*)d_in[10];
    const float* W1   = (const float*)d_in[11];
    const float* b1   = (const float*)d_in[12];
    const float* W2   = (const float*)d_in[13];
    const float* b2   = (const float*)d_in[14];
    const float* ln2g = (const float*)d_in[15];
    const float* ln2b = (const float*)d_in[16];
    float* out = (float*)d_out;

    float *xn, *qb, *kb, *vb, *ctx, *x1, *x2, *hb;
    cudaGetSymbolAddress((void**)&xn,  g_xn);
    cudaGetSymbolAddress((void**)&qb,  g_q);
    cudaGetSymbolAddress((void**)&kb,  g_k);
    cudaGetSymbolAddress((void**)&vb,  g_v);
    cudaGetSymbolAddress((void**)&ctx, g_ctx);
    cudaGetSymbolAddress((void**)&x1,  g_x1);
    cudaGetSymbolAddress((void**)&x2,  g_x2);
    cudaGetSymbolAddress((void**)&hb,  g_h);

    cudaFuncSetAttribute(attn_kernel, cudaFuncAttributeMaxDynamicSharedMemorySize, ATTN_SMEM);

    dim3 gsq(EMB / 128, SLEN / 128);           // 16 x 16
    dim3 gff(DFF / 128, SLEN / 128);           // 64 x 16

    ln_kernel<<<SLEN, 256>>>(x, ln1g, ln1b, xn);
    gemm_kernel<0><<<gsq, 256>>>(xn, Wq, bq, nullptr, qb, SLEN, EMB, EMB);
    gemm_kernel<0><<<gsq, 256>>>(xn, Wk, bk, nullptr, kb, SLEN, EMB, EMB);
    gemm_kernel<0><<<gsq, 256>>>(xn, Wv, bv, nullptr, vb, SLEN, EMB, EMB);
    attn_kernel<<<dim3(SLEN / 64, NHEAD), 256, ATTN_SMEM>>>(qb, kb, vb, ctx);
    gemm_kernel<1><<<gsq, 256>>>(ctx, Wo, bo, xn, x1, SLEN, EMB, EMB);
    ln_kernel<<<SLEN, 256>>>(x1, ln2g, ln2b, x2);
    gemm_kernel<2><<<gff, 256>>>(x2, W1, b1, nullptr, hb, SLEN, DFF, EMB);
    gemm_kernel<1><<<gsq, 256>>>(hb, W2, b2, x1, out, SLEN, EMB, DFF);
}

// round 3
// speedup vs baseline: 1.9678x; 1.9678x over previous
#include <cuda_runtime.h>
#include <cuda_bf16.h>
#include <math.h>
#include <stdint.h>

#define SLEN  2048
#define EMB   2048
#define DFF   8192
#define NHEAD 16
#define HDIM  128
#define WIN   512
#define LNEPS 1e-5f

// ---------------- fp32 scratch ----------------
__device__ float g_xn [SLEN*EMB];
__device__ float g_q  [SLEN*EMB];
__device__ float g_k  [SLEN*EMB];
__device__ float g_v  [SLEN*EMB];
__device__ float g_ctx[SLEN*EMB];
__device__ float g_x1 [SLEN*EMB];
__device__ float g_x2 [SLEN*EMB];
__device__ float g_h  [SLEN*DFF];

// ---------------- bf16 split scratch ----------------
__device__ __nv_bfloat16 g_xn_h [SLEN*EMB], g_xn_l [SLEN*EMB];
__device__ __nv_bfloat16 g_ctx_h[SLEN*EMB], g_ctx_l[SLEN*EMB];
__device__ __nv_bfloat16 g_x2_h [SLEN*EMB], g_x2_l [SLEN*EMB];
__device__ __nv_bfloat16 g_h_h  [SLEN*DFF], g_h_l  [SLEN*DFF];
__device__ __nv_bfloat16 g_WqT_h[EMB*EMB],  g_WqT_l[EMB*EMB];
__device__ __nv_bfloat16 g_WkT_h[EMB*EMB],  g_WkT_l[EMB*EMB];
__device__ __nv_bfloat16 g_WvT_h[EMB*EMB],  g_WvT_l[EMB*EMB];
__device__ __nv_bfloat16 g_WoT_h[EMB*EMB],  g_WoT_l[EMB*EMB];
__device__ __nv_bfloat16 g_W1T_h[EMB*DFF],  g_W1T_l[EMB*DFF];
__device__ __nv_bfloat16 g_W2T_h[DFF*EMB],  g_W2T_l[DFF*EMB];

// ================= PTX helpers (sm_100 baseline ISA only) =================
__device__ __forceinline__ uint32_t s2u(const void* p) {
    uint32_t a;
    asm("{ .reg .u64 t; cvta.to.shared.u64 t, %1; cvt.u32.u64 %0, t; }" : "=r"(a) : "l"(p));
    return a;
}
__device__ __forceinline__ void cpa16(uint32_t s, const void* g) {
    asm volatile("cp.async.cg.shared.global [%0], [%1], 16;" :: "r"(s), "l"(g));
}
__device__ __forceinline__ void cp_commit() { asm volatile("cp.async.commit_group;" ::: "memory"); }
__device__ __forceinline__ void cp_wait1()  { asm volatile("cp.async.wait_group 1;" ::: "memory"); }

__device__ __forceinline__ void ldsm4(uint32_t* r, uint32_t a) {
    asm volatile("ldmatrix.sync.aligned.m8n8.x4.shared.b16 {%0,%1,%2,%3}, [%4];"
                 : "=r"(r[0]), "=r"(r[1]), "=r"(r[2]), "=r"(r[3]) : "r"(a));
}
__device__ __forceinline__ void mma16816(float* c, const uint32_t* a, const uint32_t* b) {
    asm volatile("mma.sync.aligned.m16n8k16.row.col.f32.bf16.bf16.f32 "
                 "{%0,%1,%2,%3}, {%4,%5,%6,%7}, {%8,%9}, {%0,%1,%2,%3};"
                 : "+f"(c[0]), "+f"(c[1]), "+f"(c[2]), "+f"(c[3])
                 : "r"(a[0]), "r"(a[1]), "r"(a[2]), "r"(a[3]), "r"(b[0]), "r"(b[1]));
}

// ================= layernorm =================
__global__ void ln_kernel(const float* __restrict__ x, const float* __restrict__ gam,
                          const float* __restrict__ bet, float* __restrict__ y)
{
    int row = blockIdx.x;
    const float* xr = x + (size_t)row * EMB;
    float vals[8];
    float s = 0.f, ss = 0.f;
#pragma unroll
    for (int i = 0; i < 8; i++) {
        float v = xr[threadIdx.x + i * 256];
        vals[i] = v; s += v; ss += v * v;
    }
#pragma unroll
    for (int o = 16; o; o >>= 1) {
        s  += __shfl_xor_sync(~0u, s,  o);
        ss += __shfl_xor_sync(~0u, ss, o);
    }
    __shared__ float rs[8], rss[8];
    int warp = threadIdx.x >> 5, lane = threadIdx.x & 31;
    if (lane == 0) { rs[warp] = s; rss[warp] = ss; }
    __syncthreads();
    if (warp == 0) {
        float a  = (lane < 8) ? rs[lane]  : 0.f;
        float b2 = (lane < 8) ? rss[lane] : 0.f;
#pragma unroll
        for (int o = 4; o; o >>= 1) {
            a  += __shfl_xor_sync(~0u, a,  o);
            b2 += __shfl_xor_sync(~0u, b2, o);
        }
        if (lane == 0) { rs[0] = a; rss[0] = b2; }
    }
    __syncthreads();
    float mean = rs[0]  * (1.f / EMB);
    float var  = rss[0] * (1.f / EMB) - mean * mean;
    float inv  = rsqrtf(var + LNEPS);
    float* yr = y + (size_t)row * EMB;
#pragma unroll
    for (int i = 0; i < 8; i++) {
        int c = threadIdx.x + i * 256;
        yr[c] = (vals[i] - mean) * inv * gam[c] + bet[c];
    }
}

// ================= split-convert kernels =================
__global__ void split_kernel(const float* __restrict__ x, __nv_bfloat16* __restrict__ hi,
                             __nv_bfloat16* __restrict__ lo)
{
    int i = (blockIdx.x * 256 + threadIdx.x) << 2;
    float4 v = *(const float4*)(x + i);
    __nv_bfloat16 h0 = __float2bfloat16(v.x), h1 = __float2bfloat16(v.y);
    __nv_bfloat16 h2 = __float2bfloat16(v.z), h3 = __float2bfloat16(v.w);
    __nv_bfloat16 l0 = __float2bfloat16(v.x - __bfloat162float(h0));
    __nv_bfloat16 l1 = __float2bfloat16(v.y - __bfloat162float(h1));
    __nv_bfloat16 l2 = __float2bfloat16(v.z - __bfloat162float(h2));
    __nv_bfloat16 l3 = __float2bfloat16(v.w - __bfloat162float(h3));
    *(__nv_bfloat162*)(hi + i)     = __nv_bfloat162(h0, h1);
    *(__nv_bfloat162*)(hi + i + 2) = __nv_bfloat162(h2, h3);
    *(__nv_bfloat162*)(lo + i)     = __nv_bfloat162(l0, l1);
    *(__nv_bfloat162*)(lo + i + 2) = __nv_bfloat162(l2, l3);
}

// transpose + split: W [K,N] row-major -> WT hi/lo [N,K]
__global__ void splitT_kernel(const float* __restrict__ W, __nv_bfloat16* __restrict__ ht,
                              __nv_bfloat16* __restrict__ lt, int K, int N)
{
    __shared__ float t[32][33];
    int k0 = blockIdx.y * 32, n0 = blockIdx.x * 32;
    int tx = threadIdx.x & 31, ty = threadIdx.x >> 5;
#pragma unroll
    for (int i = 0; i < 4; i++) {
        int r = ty + i * 8;
        t[r][tx] = W[(size_t)(k0 + r) * N + n0 + tx];
    }
    __syncthreads();
#pragma unroll
    for (int i = 0; i < 4; i++) {
        int r = ty + i * 8;
        float v = t[tx][r];
        __nv_bfloat16 hv = __float2bfloat16(v);
        __nv_bfloat16 lv = __float2bfloat16(v - __bfloat162float(hv));
        size_t o = (size_t)(n0 + r) * K + k0 + tx;
        ht[o] = hv; lt[o] = lv;
    }
}

// ================= split-bf16 mma.sync GEMM =================
// C[M,N] = A[M,K] @ B^T  with B stored [N,K]; A,B pre-split into hi+lo bf16.
// 3 passes fused: AhBh + AhBl + AlBh, fp32 accumulators.
#define BK      32
#define TSTRB   80                  // 32 bf16 = 64B + 16B pad per row
#define TILEB   (128 * TSTRB)       // 10240 B
#define STAGES  3
#define STAGEB  (4 * TILEB)         // Ah, Al, Bh, Bl
#define GEMM_SMEM (STAGES * STAGEB) // 122880 B

__device__ __forceinline__ void load_stage(
    uint32_t sb, int st, int kt,
    const __nv_bfloat16* Ah, const __nv_bfloat16* Al,
    const __nv_bfloat16* Bh, const __nv_bfloat16* Bl,
    int m0, int n0, int K)
{
    const int t = threadIdx.x;
    uint32_t s0 = sb + st * STAGEB;
    const __nv_bfloat16* gp[4] = {
        Ah + (size_t)m0 * K, Al + (size_t)m0 * K,
        Bh + (size_t)n0 * K, Bl + (size_t)n0 * K };
    const size_t kof = (size_t)kt * BK;
#pragma unroll
    for (int tile = 0; tile < 4; tile++) {
        const __nv_bfloat16* g = gp[tile] + kof;
#pragma unroll
        for (int i = 0; i < 2; i++) {
            int c = t + 256 * i;             // 512 chunks of 16B per tile
            int row = c >> 2, off = c & 3;
            cpa16(s0 + tile * TILEB + row * TSTRB + off * 16,
                  g + (size_t)row * K + off * 8);
        }
    }
}

__device__ __forceinline__ float gelu_exact(float v) {
    return 0.5f * v * (1.0f + erff(v * 0.70710678118654752440f));
}

// EPI: 0 = +bias, 1 = +bias+residual, 2 = +bias then GELU
template<int EPI>
__global__ void __launch_bounds__(256, 1) gemm_bf16s(
    const __nv_bfloat16* __restrict__ Ah, const __nv_bfloat16* __restrict__ Al,
    const __nv_bfloat16* __restrict__ Bh, const __nv_bfloat16* __restrict__ Bl,
    const float* __restrict__ bias, const float* __restrict__ res,
    float* __restrict__ C, int M, int N, int K)
{
    extern __shared__ __align__(128) char sm_[];
    uint32_t sb = s2u(sm_);
    const int m0 = blockIdx.y * 128, n0 = blockIdx.x * 128;
    const int w = threadIdx.x >> 5, lane = threadIdx.x & 31;
    const int wm = w >> 1, wn = w & 1;           // 4 x 2 warp grid

    // ldmatrix per-lane address components
    const int arow = (lane & 7) + ((lane >> 3) & 1) * 8;
    const int acol = ((lane >> 4) & 1) * 16;
    const int brow = (lane & 7) + ((lane >> 4) & 1) * 8;
    const int bcol = ((lane >> 3) & 1) * 16;

    float acc[2][8][4];
#pragma unroll
    for (int i = 0; i < 2; i++)
#pragma unroll
        for (int j = 0; j < 8; j++)
#pragma unroll
            for (int r = 0; r < 4; r++) acc[i][j][r] = 0.f;

    const int KT = K / BK;
    load_stage(sb, 0, 0, Ah, Al, Bh, Bl, m0, n0, K); cp_commit();
    load_stage(sb, 1, 1, Ah, Al, Bh, Bl, m0, n0, K); cp_commit();

    for (int kt = 0; kt < KT; kt++) {
        cp_wait1();
        __syncthreads();
        if (kt + 2 < KT) load_stage(sb, (kt + 2) % STAGES, kt + 2, Ah, Al, Bh, Bl, m0, n0, K);
        cp_commit();

        uint32_t s0  = sb + (kt % STAGES) * STAGEB;
        uint32_t sah = s0;
        uint32_t sal = s0 + TILEB;
        uint32_t sbh = s0 + 2 * TILEB;
        uint32_t sbl = s0 + 3 * TILEB;

#pragma unroll
        for (int ks = 0; ks < 2; ks++) {
            uint32_t ah[2][4], al[2][4];
#pragma unroll
            for (int mt = 0; mt < 2; mt++) {
                uint32_t ro = (wm * 32 + mt * 16 + arow) * TSTRB + acol + ks * 32;
                ldsm4(ah[mt], sah + ro);
                ldsm4(al[mt], sal + ro);
            }
#pragma unroll
            for (int bt = 0; bt < 4; bt++) {
                uint32_t bh[4], bl[4];
                uint32_t ro = (wn * 64 + bt * 16 + brow) * TSTRB + bcol + ks * 32;
                ldsm4(bh, sbh + ro);
                ldsm4(bl, sbl + ro);
#pragma unroll
                for (int mt = 0; mt < 2; mt++) {
#pragma unroll
                    for (int nt = 0; nt < 2; nt++) {
                        float* c = acc[mt][bt * 2 + nt];
                        mma16816(c, ah[mt], bh + nt * 2);
                        mma16816(c, ah[mt], bl + nt * 2);
                        mma16816(c, al[mt], bh + nt * 2);
                    }
                }
            }
        }
    }

    // ---------- epilogue ----------
    const int g = lane >> 2, tq = lane & 3;
#pragma unroll
    for (int mt = 0; mt < 2; mt++) {
        int r0 = m0 + wm * 32 + mt * 16 + g;
#pragma unroll
        for (int j = 0; j < 8; j++) {
            int col = n0 + wn * 64 + j * 8 + tq * 2;
            float b0 = __ldg(bias + col), b1 = __ldg(bias + col + 1);
            float v0 = acc[mt][j][0] + b0, v1 = acc[mt][j][1] + b1;
            float v2 = acc[mt][j][2] + b0, v3 = acc[mt][j][3] + b1;
            if (EPI == 1) {
                const float* r = res + (size_t)r0 * N + col;
                v0 += r[0]; v1 += r[1];
                v2 += r[(size_t)8 * N]; v3 += r[(size_t)8 * N + 1];
            }
            if (EPI == 2) {
                v0 = gelu_exact(v0); v1 = gelu_exact(v1);
                v2 = gelu_exact(v2); v3 = gelu_exact(v3);
            }
            *(float2*)&C[(size_t)r0 * N + col]       = make_float2(v0, v1);
            *(float2*)&C[(size_t)(r0 + 8) * N + col] = make_float2(v2, v3);
        }
    }
}

// ================= fused sliding-window attention (fp32) =================
#define QT_STR 68
#define VS_STR 132
#define PS_STR 65
#define ATTN_SMEM ((128*QT_STR*2 + 64*VS_STR + 64*PS_STR) * 4)
#define QK_SCALE 0.08838834764831845f

__global__ void __launch_bounds__(256) attn_kernel(
    const float* __restrict__ q, const float* __restrict__ k,
    const float* __restrict__ v, float* __restrict__ ctx)
{
    extern __shared__ float sm[];
    float* Qt = sm;
    float* Kt = Qt + 128 * QT_STR;
    float* Vs = Kt + 128 * QT_STR;
    float* Ps = Vs + 64 * VS_STR;

    const int h = blockIdx.y, qt = blockIdx.x;
    const int q0 = qt * 64;
    const int tid  = threadIdx.x;
    const int warp = tid >> 5, lane = tid & 31;
    const int tr = tid >> 4, tc = tid & 15;

#pragma unroll
    for (int rr = 0; rr < 8; rr++) {
        int r = warp * 8 + rr;
        float4 qv = *(const float4*)&q[(size_t)(q0 + r) * EMB + h * HDIM + lane * 4];
        Qt[(lane * 4 + 0) * QT_STR + r] = qv.x * QK_SCALE;
        Qt[(lane * 4 + 1) * QT_STR + r] = qv.y * QK_SCALE;
        Qt[(lane * 4 + 2) * QT_STR + r] = qv.z * QK_SCALE;
        Qt[(lane * 4 + 3) * QT_STR + r] = qv.w * QK_SCALE;
    }

    float m_i[4], l_i[4], o[4][8];
#pragma unroll
    for (int ii = 0; ii < 4; ii++) {
        m_i[ii] = -1e30f; l_i[ii] = 0.f;
#pragma unroll
        for (int dd = 0; dd < 8; dd++) o[ii][dd] = 0.f;
    }

    const int kt0 = (q0 > WIN) ? ((q0 - WIN) >> 6) : 0;
    for (int kt = kt0; kt <= qt; kt++) {
        const int j0 = kt * 64;
        __syncthreads();
#pragma unroll
        for (int rr = 0; rr < 8; rr++) {
            int r = warp * 8 + rr;
            float4 kv = *(const float4*)&k[(size_t)(j0 + r) * EMB + h * HDIM + lane * 4];
            Kt[(lane * 4 + 0) * QT_STR + r] = kv.x;
            Kt[(lane * 4 + 1) * QT_STR + r] = kv.y;
            Kt[(lane * 4 + 2) * QT_STR + r] = kv.z;
            Kt[(lane * 4 + 3) * QT_STR + r] = kv.w;
            float4 vv = *(const float4*)&v[(size_t)(j0 + r) * EMB + h * HDIM + lane * 4];
            *(float4*)&Vs[r * VS_STR + lane * 4] = vv;
        }
        __syncthreads();

        float sacc[4][4];
#pragma unroll
        for (int ii = 0; ii < 4; ii++)
#pragma unroll
            for (int jj = 0; jj < 4; jj++) sacc[ii][jj] = 0.f;
#pragma unroll 8
        for (int d = 0; d < 128; d++) {
            float4 a = *(const float4*)&Qt[d * QT_STR + tr * 4];
            float4 b = *(const float4*)&Kt[d * QT_STR + tc * 4];
            float av[4] = {a.x, a.y, a.z, a.w};
            float bv[4] = {b.x, b.y, b.z, b.w};
#pragma unroll
            for (int ii = 0; ii < 4; ii++)
#pragma unroll
                for (int jj = 0; jj < 4; jj++)
                    sacc[ii][jj] = fmaf(av[ii], bv[jj], sacc[ii][jj]);
        }

#pragma unroll
        for (int ii = 0; ii < 4; ii++) {
            const int i = q0 + tr * 4 + ii;
            bool bn[4];
            float rmax = -1e30f;
#pragma unroll
            for (int jj = 0; jj < 4; jj++) {
                int j = j0 + tc * 4 + jj;
                bn[jj] = (j > i) || (i - j > WIN);
                float val = bn[jj] ? -1e30f : sacc[ii][jj];
                sacc[ii][jj] = val;
                rmax = fmaxf(rmax, val);
            }
#pragma unroll
            for (int off = 8; off; off >>= 1)
                rmax = fmaxf(rmax, __shfl_xor_sync(~0u, rmax, off));
            float mnew  = fmaxf(m_i[ii], rmax);
            float alpha = __expf(m_i[ii] - mnew);
            float rsum = 0.f;
#pragma unroll
            for (int jj = 0; jj < 4; jj++) {
                float p = bn[jj] ? 0.f : __expf(sacc[ii][jj] - mnew);
                Ps[(tr * 4 + ii) * PS_STR + tc * 4 + jj] = p;
                rsum += p;
            }
#pragma unroll
            for (int off = 8; off; off >>= 1)
                rsum += __shfl_xor_sync(~0u, rsum, off);
            l_i[ii] = l_i[ii] * alpha + rsum;
            m_i[ii] = mnew;
#pragma unroll
            for (int dd = 0; dd < 8; dd++) o[ii][dd] *= alpha;
        }
        __syncthreads();

#pragma unroll 8
        for (int kk = 0; kk < 64; kk++) {
            float4 v0 = *(const float4*)&Vs[kk * VS_STR + tc * 8];
            float4 v1 = *(const float4*)&Vs[kk * VS_STR + tc * 8 + 4];
#pragma unroll
            for (int ii = 0; ii < 4; ii++) {
                float p = Ps[(tr * 4 + ii) * PS_STR + kk];
                o[ii][0] = fmaf(p, v0.x, o[ii][0]);
                o[ii][1] = fmaf(p, v0.y, o[ii][1]);
                o[ii][2] = fmaf(p, v0.z, o[ii][2]);
                o[ii][3] = fmaf(p, v0.w, o[ii][3]);
                o[ii][4] = fmaf(p, v1.x, o[ii][4]);
                o[ii][5] = fmaf(p, v1.y, o[ii][5]);
                o[ii][6] = fmaf(p, v1.z, o[ii][6]);
                o[ii][7] = fmaf(p, v1.w, o[ii][7]);
            }
        }
    }

#pragma unroll
    for (int ii = 0; ii < 4; ii++) {
        float inv = 1.f / l_i[ii];
        size_t base = (size_t)(q0 + tr * 4 + ii) * EMB + h * HDIM + tc * 8;
        *(float4*)&ctx[base]     = make_float4(o[ii][0]*inv, o[ii][1]*inv, o[ii][2]*inv, o[ii][3]*inv);
        *(float4*)&ctx[base + 4] = make_float4(o[ii][4]*inv, o[ii][5]*inv, o[ii][6]*inv, o[ii][7]*inv);
    }
}

// ================= launch =================
extern "C" void kernel_launch(void* const* d_in, const int* in_sizes, int n_in,
                              void* d_out, int out_size)
{
    const float* x    = (const float*)d_in[0];
    const float* Wq   = (const float*)d_in[1];
    const float* bq   = (const float*)d_in[2];
    const float* Wk   = (const float*)d_in[3];
    const float* bk   = (const float*)d_in[4];
    const float* Wv   = (const float*)d_in[5];
    const float* bv   = (const float*)d_in[6];
    const float* Wo   = (const float*)d_in[7];
    const float* bo   = (const float*)d_in[8];
    const float* ln1g = (const float*)d_in[9];
    const float* ln1b = (const float*)d_in[10];
    const float* W1   = (const float*)d_in[11];
    const float* b1   = (const float*)d_in[12];
    const float* W2   = (const float*)d_in[13];
    const float* b2   = (const float*)d_in[14];
    const float* ln2g = (const float*)d_in[15];
    const float* ln2b = (const float*)d_in[16];
    float* out = (float*)d_out;

    float *xn, *qb, *kb, *vb, *ctx, *x1, *x2, *hb;
    cudaGetSymbolAddress((void**)&xn,  g_xn);
    cudaGetSymbolAddress((void**)&qb,  g_q);
    cudaGetSymbolAddress((void**)&kb,  g_k);
    cudaGetSymbolAddress((void**)&vb,  g_v);
    cudaGetSymbolAddress((void**)&ctx, g_ctx);
    cudaGetSymbolAddress((void**)&x1,  g_x1);
    cudaGetSymbolAddress((void**)&x2,  g_x2);
    cudaGetSymbolAddress((void**)&hb,  g_h);

    __nv_bfloat16 *xnh, *xnl, *ctxh, *ctxl, *x2h, *x2l, *hh, *hl;
    __nv_bfloat16 *wqh, *wql, *wkh, *wkl, *wvh, *wvl, *woh, *wol, *w1h, *w1l, *w2h, *w2l;
    cudaGetSymbolAddress((void**)&xnh,  g_xn_h);  cudaGetSymbolAddress((void**)&xnl,  g_xn_l);
    cudaGetSymbolAddress((void**)&ctxh, g_ctx_h); cudaGetSymbolAddress((void**)&ctxl, g_ctx_l);
    cudaGetSymbolAddress((void**)&x2h,  g_x2_h);  cudaGetSymbolAddress((void**)&x2l,  g_x2_l);
    cudaGetSymbolAddress((void**)&hh,   g_h_h);   cudaGetSymbolAddress((void**)&hl,   g_h_l);
    cudaGetSymbolAddress((void**)&wqh,  g_WqT_h); cudaGetSymbolAddress((void**)&wql,  g_WqT_l);
    cudaGetSymbolAddress((void**)&wkh,  g_WkT_h); cudaGetSymbolAddress((void**)&wkl,  g_WkT_l);
    cudaGetSymbolAddress((void**)&wvh,  g_WvT_h); cudaGetSymbolAddress((void**)&wvl,  g_WvT_l);
    cudaGetSymbolAddress((void**)&woh,  g_WoT_h); cudaGetSymbolAddress((void**)&wol,  g_WoT_l);
    cudaGetSymbolAddress((void**)&w1h,  g_W1T_h); cudaGetSymbolAddress((void**)&w1l,  g_W1T_l);
    cudaGetSymbolAddress((void**)&w2h,  g_W2T_h); cudaGetSymbolAddress((void**)&w2l,  g_W2T_l);

    cudaFuncSetAttribute(attn_kernel,   cudaFuncAttributeMaxDynamicSharedMemorySize, ATTN_SMEM);
    cudaFuncSetAttribute(gemm_bf16s<0>, cudaFuncAttributeMaxDynamicSharedMemorySize, GEMM_SMEM);
    cudaFuncSetAttribute(gemm_bf16s<1>, cudaFuncAttributeMaxDynamicSharedMemorySize, GEMM_SMEM);
    cudaFuncSetAttribute(gemm_bf16s<2>, cudaFuncAttributeMaxDynamicSharedMemorySize, GEMM_SMEM);

    const int nEE = SLEN * EMB;
    const int nEF = SLEN * DFF;

    dim3 gsq(EMB / 128, SLEN / 128);   // 16 x 16
    dim3 gf1(DFF / 128, SLEN / 128);   // 64 x 16
    dim3 tEE(EMB / 32, EMB / 32);
    dim3 tE_F(DFF / 32, EMB / 32);
    dim3 tF_E(EMB / 32, DFF / 32);

    splitT_kernel<<<tEE, 256>>>(Wq, wqh, wql, EMB, EMB);
    splitT_kernel<<<tEE, 256>>>(Wk, wkh, wkl, EMB, EMB);
    splitT_kernel<<<tEE, 256>>>(Wv, wvh, wvl, EMB, EMB);
    splitT_kernel<<<tEE, 256>>>(Wo, woh, wol, EMB, EMB);
    splitT_kernel<<<tE_F, 256>>>(W1, w1h, w1l, EMB, DFF);
    splitT_kernel<<<tF_E, 256>>>(W2, w2h, w2l, DFF, EMB);

    ln_kernel<<<SLEN, 256>>>(x, ln1g, ln1b, xn);
    split_kernel<<<nEE / 1024, 256>>>(xn, xnh, xnl);

    gemm_bf16s<0><<<gsq, 256, GEMM_SMEM>>>(xnh, xnl, wqh, wql, bq, nullptr, qb, SLEN, EMB, EMB);
    gemm_bf16s<0><<<gsq, 256, GEMM_SMEM>>>(xnh, xnl, wkh, wkl, bk, nullptr, kb, SLEN, EMB, EMB);
    gemm_bf16s<0><<<gsq, 256, GEMM_SMEM>>>(xnh, xnl, wvh, wvl, bv, nullptr, vb, SLEN, EMB, EMB);

    attn_kernel<<<dim3(SLEN / 64, NHEAD), 256, ATTN_SMEM>>>(qb, kb, vb, ctx);

    split_kernel<<<nEE / 1024, 256>>>(ctx, ctxh, ctxl);
    gemm_bf16s<1><<<gsq, 256, GEMM_SMEM>>>(ctxh, ctxl, woh, wol, bo, xn, x1, SLEN, EMB, EMB);

    ln_kernel<<<SLEN, 256>>>(x1, ln2g, ln2b, x2);
    split_kernel<<<nEE / 1024, 256>>>(x2, x2h, x2l);

    gemm_bf16s<2><<<gf1, 256, GEMM_SMEM>>>(x2h, x2l, w1h, w1l, b1, nullptr, hb, SLEN, DFF, EMB);
    split_kernel<<<nEF / 1024, 256>>>(hb, hh, hl);
    gemm_bf16s<1><<<gsq, 256, GEMM_SMEM>>>(hh, hl, w2h, w2l, b2, x1, out, SLEN, EMB, DFF);
}

// round 4
// speedup vs baseline: 2.1688x; 1.1022x over previous
#include <cuda_runtime.h>
#include <cuda_bf16.h>
#include <math.h>
#include <stdint.h>

#define SLEN  2048
#define EMB   2048
#define DFF   8192
#define NHEAD 16
#define HDIM  128
#define WIN   512
#define LNEPS 1e-5f

// ---------------- fp32 scratch ----------------
__device__ float g_xn [SLEN*EMB];
__device__ float g_q  [SLEN*EMB];
__device__ float g_k  [SLEN*EMB];
__device__ float g_v  [SLEN*EMB];
__device__ float g_x1 [SLEN*EMB];

// ---------------- bf16 split scratch ----------------
__device__ __nv_bfloat16 g_xn_h [SLEN*EMB], g_xn_l [SLEN*EMB];
__device__ __nv_bfloat16 g_ctx_h[SLEN*EMB], g_ctx_l[SLEN*EMB];
__device__ __nv_bfloat16 g_x2_h [SLEN*EMB], g_x2_l [SLEN*EMB];
__device__ __nv_bfloat16 g_h_h  [SLEN*DFF], g_h_l  [SLEN*DFF];
__device__ __nv_bfloat16 g_WqT_h[EMB*EMB],  g_WqT_l[EMB*EMB];
__device__ __nv_bfloat16 g_WkT_h[EMB*EMB],  g_WkT_l[EMB*EMB];
__device__ __nv_bfloat16 g_WvT_h[EMB*EMB],  g_WvT_l[EMB*EMB];
__device__ __nv_bfloat16 g_WoT_h[EMB*EMB],  g_WoT_l[EMB*EMB];
__device__ __nv_bfloat16 g_W1T_h[EMB*DFF],  g_W1T_l[EMB*DFF];
__device__ __nv_bfloat16 g_W2T_h[DFF*EMB],  g_W2T_l[DFF*EMB];

// ================= PTX helpers =================
__device__ __forceinline__ uint32_t s2u(const void* p) {
    uint32_t a;
    asm("{ .reg .u64 t; cvta.to.shared.u64 t, %1; cvt.u32.u64 %0, t; }" : "=r"(a) : "l"(p));
    return a;
}
__device__ __forceinline__ void cpa16(uint32_t s, const void* g) {
    asm volatile("cp.async.cg.shared.global [%0], [%1], 16;" :: "r"(s), "l"(g));
}
__device__ __forceinline__ void cp_commit() { asm volatile("cp.async.commit_group;" ::: "memory"); }
__device__ __forceinline__ void cp_wait1()  { asm volatile("cp.async.wait_group 1;" ::: "memory"); }
__device__ __forceinline__ void cp_wait0()  { asm volatile("cp.async.wait_group 0;" ::: "memory"); }

__device__ __forceinline__ void ldsm4(uint32_t* r, uint32_t a) {
    asm volatile("ldmatrix.sync.aligned.m8n8.x4.shared.b16 {%0,%1,%2,%3}, [%4];"
                 : "=r"(r[0]), "=r"(r[1]), "=r"(r[2]), "=r"(r[3]) : "r"(a));
}
__device__ __forceinline__ void mma16816(float* c, const uint32_t* a, const uint32_t* b) {
    asm volatile("mma.sync.aligned.m16n8k16.row.col.f32.bf16.bf16.f32 "
                 "{%0,%1,%2,%3}, {%4,%5,%6,%7}, {%8,%9}, {%0,%1,%2,%3};"
                 : "+f"(c[0]), "+f"(c[1]), "+f"(c[2]), "+f"(c[3])
                 : "r"(a[0]), "r"(a[1]), "r"(a[2]), "r"(a[3]), "r"(b[0]), "r"(b[1]));
}
__device__ __forceinline__ void split1(float v, __nv_bfloat16& h, __nv_bfloat16& l) {
    h = __float2bfloat16(v);
    l = __float2bfloat16(v - __bfloat162float(h));
}

// ================= layernorm (optionally fused split) =================
template<bool FP32OUT>
__global__ void ln_kernel(const float* __restrict__ x, const float* __restrict__ gam,
                          const float* __restrict__ bet, float* __restrict__ y,
                          __nv_bfloat16* __restrict__ hi, __nv_bfloat16* __restrict__ lo)
{
    int row = blockIdx.x;
    const float* xr = x + (size_t)row * EMB;
    float vals[8];
    float s = 0.f, ss = 0.f;
#pragma unroll
    for (int i = 0; i < 8; i++) {
        float v = xr[threadIdx.x + i * 256];
        vals[i] = v; s += v; ss += v * v;
    }
#pragma unroll
    for (int o = 16; o; o >>= 1) {
        s  += __shfl_xor_sync(~0u, s,  o);
        ss += __shfl_xor_sync(~0u, ss, o);
    }
    __shared__ float rs[8], rss[8];
    int warp = threadIdx.x >> 5, lane = threadIdx.x & 31;
    if (lane == 0) { rs[warp] = s; rss[warp] = ss; }
    __syncthreads();
    if (warp == 0) {
        float a  = (lane < 8) ? rs[lane]  : 0.f;
        float b2 = (lane < 8) ? rss[lane] : 0.f;
#pragma unroll
        for (int o = 4; o; o >>= 1) {
            a  += __shfl_xor_sync(~0u, a,  o);
            b2 += __shfl_xor_sync(~0u, b2, o);
        }
        if (lane == 0) { rs[0] = a; rss[0] = b2; }
    }
    __syncthreads();
    float mean = rs[0]  * (1.f / EMB);
    float var  = rss[0] * (1.f / EMB) - mean * mean;
    float inv  = rsqrtf(var + LNEPS);
#pragma unroll
    for (int i = 0; i < 8; i++) {
        int c = threadIdx.x + i * 256;
        float v = (vals[i] - mean) * inv * gam[c] + bet[c];
        if (FP32OUT) y[(size_t)row * EMB + c] = v;
        __nv_bfloat16 h, l;
        split1(v, h, l);
        hi[(size_t)row * EMB + c] = h;
        lo[(size_t)row * EMB + c] = l;
    }
}

// ================= weight transpose + split =================
__global__ void splitT_kernel(const float* __restrict__ W, __nv_bfloat16* __restrict__ ht,
                              __nv_bfloat16* __restrict__ lt, int K, int N)
{
    __shared__ float t[32][33];
    int k0 = blockIdx.y * 32, n0 = blockIdx.x * 32;
    int tx = threadIdx.x & 31, ty = threadIdx.x >> 5;
#pragma unroll
    for (int i = 0; i < 4; i++) {
        int r = ty + i * 8;
        t[r][tx] = W[(size_t)(k0 + r) * N + n0 + tx];
    }
    __syncthreads();
#pragma unroll
    for (int i = 0; i < 4; i++) {
        int r = ty + i * 8;
        float v = t[tx][r];
        __nv_bfloat16 hv, lv;
        split1(v, hv, lv);
        size_t o = (size_t)(n0 + r) * K + k0 + tx;
        ht[o] = hv; lt[o] = lv;
    }
}

// ================= split-bf16 mma.sync GEMM (2-stage, 2 CTA/SM) =================
#define BK      32
#define TSTRB   80
#define TILEB   (128 * TSTRB)       // 10240 B
#define STAGES  2
#define STAGEB  (4 * TILEB)         // 40960 B
#define GEMM_SMEM (STAGES * STAGEB) // 81920 B

__device__ __forceinline__ void load_stage(
    uint32_t sb, int st, int kt,
    const __nv_bfloat16* Ah, const __nv_bfloat16* Al,
    const __nv_bfloat16* Bh, const __nv_bfloat16* Bl,
    int m0, int n0, int K)
{
    const int t = threadIdx.x;
    uint32_t s0 = sb + st * STAGEB;
    const __nv_bfloat16* gp[4] = {
        Ah + (size_t)m0 * K, Al + (size_t)m0 * K,
        Bh + (size_t)n0 * K, Bl + (size_t)n0 * K };
    const size_t kof = (size_t)kt * BK;
#pragma unroll
    for (int tile = 0; tile < 4; tile++) {
        const __nv_bfloat16* g = gp[tile] + kof;
#pragma unroll
        for (int i = 0; i < 2; i++) {
            int c = t + 256 * i;
            int row = c >> 2, off = c & 3;
            cpa16(s0 + tile * TILEB + row * TSTRB + off * 16,
                  g + (size_t)row * K + off * 8);
        }
    }
}

__device__ __forceinline__ float gelu_exact(float v) {
    return 0.5f * v * (1.0f + erff(v * 0.70710678118654752440f));
}

// EPI: 0 = +bias -> fp32 C
//      1 = +bias+residual -> fp32 C
//      2 = +bias, GELU -> split bf16 (Ch, Cl)
template<int EPI>
__global__ void __launch_bounds__(256, 2) gemm_bf16s(
    const __nv_bfloat16* __restrict__ Ah, const __nv_bfloat16* __restrict__ Al,
    const __nv_bfloat16* __restrict__ Bh, const __nv_bfloat16* __restrict__ Bl,
    const float* __restrict__ bias, const float* __restrict__ res,
    float* __restrict__ C, __nv_bfloat16* __restrict__ Ch, __nv_bfloat16* __restrict__ Cl,
    int M, int N, int K)
{
    extern __shared__ __align__(128) char sm_[];
    uint32_t sb = s2u(sm_);
    const int m0 = blockIdx.y * 128, n0 = blockIdx.x * 128;
    const int w = threadIdx.x >> 5, lane = threadIdx.x & 31;
    const int wm = w >> 1, wn = w & 1;

    const int arow = (lane & 7) + ((lane >> 3) & 1) * 8;
    const int acol = ((lane >> 4) & 1) * 16;
    const int brow = (lane & 7) + ((lane >> 4) & 1) * 8;
    const int bcol = ((lane >> 3) & 1) * 16;

    float acc[2][8][4];
#pragma unroll
    for (int i = 0; i < 2; i++)
#pragma unroll
        for (int j = 0; j < 8; j++)
#pragma unroll
            for (int r = 0; r < 4; r++) acc[i][j][r] = 0.f;

    const int KT = K / BK;
    load_stage(sb, 0, 0, Ah, Al, Bh, Bl, m0, n0, K); cp_commit();
    load_stage(sb, 1, 1, Ah, Al, Bh, Bl, m0, n0, K); cp_commit();

    for (int kt = 0; kt < KT; kt++) {
        if (kt + 1 < KT) cp_wait1(); else cp_wait0();
        __syncthreads();

        uint32_t s0  = sb + (kt & 1) * STAGEB;
        uint32_t sah = s0;
        uint32_t sal = s0 + TILEB;
        uint32_t sbh = s0 + 2 * TILEB;
        uint32_t sbl = s0 + 3 * TILEB;

#pragma unroll
        for (int ks = 0; ks < 2; ks++) {
            uint32_t ah[2][4], al[2][4];
#pragma unroll
            for (int mt = 0; mt < 2; mt++) {
                uint32_t ro = (wm * 32 + mt * 16 + arow) * TSTRB + acol + ks * 32;
                ldsm4(ah[mt], sah + ro);
                ldsm4(al[mt], sal + ro);
            }
#pragma unroll
            for (int bt = 0; bt < 4; bt++) {
                uint32_t bh[4], bl[4];
                uint32_t ro = (wn * 64 + bt * 16 + brow) * TSTRB + bcol + ks * 32;
                ldsm4(bh, sbh + ro);
                ldsm4(bl, sbl + ro);
                // pass 1: Ah*Bh (4 independent MMAs)
#pragma unroll
                for (int mt = 0; mt < 2; mt++)
#pragma unroll
                    for (int nt = 0; nt < 2; nt++)
                        mma16816(acc[mt][bt * 2 + nt], ah[mt], bh + nt * 2);
                // pass 2: Ah*Bl
#pragma unroll
                for (int mt = 0; mt < 2; mt++)
#pragma unroll
                    for (int nt = 0; nt < 2; nt++)
                        mma16816(acc[mt][bt * 2 + nt], ah[mt], bl + nt * 2);
                // pass 3: Al*Bh
#pragma unroll
                for (int mt = 0; mt < 2; mt++)
#pragma unroll
                    for (int nt = 0; nt < 2; nt++)
                        mma16816(acc[mt][bt * 2 + nt], al[mt], bh + nt * 2);
            }
        }
        __syncthreads();
        if (kt + 2 < KT) {
            load_stage(sb, kt & 1, kt + 2, Ah, Al, Bh, Bl, m0, n0, K);
            cp_commit();
        }
    }

    // ---------- epilogue ----------
    const int g = lane >> 2, tq = lane & 3;
#pragma unroll
    for (int mt = 0; mt < 2; mt++) {
        int r0 = m0 + wm * 32 + mt * 16 + g;
#pragma unroll
        for (int j = 0; j < 8; j++) {
            int col = n0 + wn * 64 + j * 8 + tq * 2;
            float b0 = __ldg(bias + col), b1 = __ldg(bias + col + 1);
            float v0 = acc[mt][j][0] + b0, v1 = acc[mt][j][1] + b1;
            float v2 = acc[mt][j][2] + b0, v3 = acc[mt][j][3] + b1;
            if (EPI == 1) {
                const float* r = res + (size_t)r0 * N + col;
                v0 += r[0]; v1 += r[1];
                v2 += r[(size_t)8 * N]; v3 += r[(size_t)8 * N + 1];
            }
            if (EPI == 2) {
                v0 = gelu_exact(v0); v1 = gelu_exact(v1);
                v2 = gelu_exact(v2); v3 = gelu_exact(v3);
                __nv_bfloat16 h0, l0, h1, l1, h2, l2, h3, l3;
                split1(v0, h0, l0); split1(v1, h1, l1);
                split1(v2, h2, l2); split1(v3, h3, l3);
                *(__nv_bfloat162*)&Ch[(size_t)r0 * N + col]       = __nv_bfloat162(h0, h1);
                *(__nv_bfloat162*)&Cl[(size_t)r0 * N + col]       = __nv_bfloat162(l0, l1);
                *(__nv_bfloat162*)&Ch[(size_t)(r0 + 8) * N + col] = __nv_bfloat162(h2, h3);
                *(__nv_bfloat162*)&Cl[(size_t)(r0 + 8) * N + col] = __nv_bfloat162(l2, l3);
            } else {
                *(float2*)&C[(size_t)r0 * N + col]       = make_float2(v0, v1);
                *(float2*)&C[(size_t)(r0 + 8) * N + col] = make_float2(v2, v3);
            }
        }
    }
}

// ================= fused sliding-window attention (fp32, split bf16 out) =================
#define QT_STR 68
#define VS_STR 132
#define PS_STR 65
#define ATTN_SMEM ((128*QT_STR*2 + 64*VS_STR + 64*PS_STR) * 4)
#define QK_SCALE 0.08838834764831845f

__global__ void __launch_bounds__(256) attn_kernel(
    const float* __restrict__ q, const float* __restrict__ k,
    const float* __restrict__ v,
    __nv_bfloat16* __restrict__ ctxh, __nv_bfloat16* __restrict__ ctxl)
{
    extern __shared__ float sm[];
    float* Qt = sm;
    float* Kt = Qt + 128 * QT_STR;
    float* Vs = Kt + 128 * QT_STR;
    float* Ps = Vs + 64 * VS_STR;

    const int h = blockIdx.y, qt = blockIdx.x;
    const int q0 = qt * 64;
    const int tid  = threadIdx.x;
    const int warp = tid >> 5, lane = tid & 31;
    const int tr = tid >> 4, tc = tid & 15;

#pragma unroll
    for (int rr = 0; rr < 8; rr++) {
        int r = warp * 8 + rr;
        float4 qv = *(const float4*)&q[(size_t)(q0 + r) * EMB + h * HDIM + lane * 4];
        Qt[(lane * 4 + 0) * QT_STR + r] = qv.x * QK_SCALE;
        Qt[(lane * 4 + 1) * QT_STR + r] = qv.y * QK_SCALE;
        Qt[(lane * 4 + 2) * QT_STR + r] = qv.z * QK_SCALE;
        Qt[(lane * 4 + 3) * QT_STR + r] = qv.w * QK_SCALE;
    }

    float m_i[4], l_i[4], o[4][8];
#pragma unroll
    for (int ii = 0; ii < 4; ii++) {
        m_i[ii] = -1e30f; l_i[ii] = 0.f;
#pragma unroll
        for (int dd = 0; dd < 8; dd++) o[ii][dd] = 0.f;
    }

    const int kt0 = (q0 > WIN) ? ((q0 - WIN) >> 6) : 0;
    for (int kt = kt0; kt <= qt; kt++) {
        const int j0 = kt * 64;
        __syncthreads();
#pragma unroll
        for (int rr = 0; rr < 8; rr++) {
            int r = warp * 8 + rr;
            float4 kv = *(const float4*)&k[(size_t)(j0 + r) * EMB + h * HDIM + lane * 4];
            Kt[(lane * 4 + 0) * QT_STR + r] = kv.x;
            Kt[(lane * 4 + 1) * QT_STR + r] = kv.y;
            Kt[(lane * 4 + 2) * QT_STR + r] = kv.z;
            Kt[(lane * 4 + 3) * QT_STR + r] = kv.w;
            float4 vv = *(const float4*)&v[(size_t)(j0 + r) * EMB + h * HDIM + lane * 4];
            *(float4*)&Vs[r * VS_STR + lane * 4] = vv;
        }
        __syncthreads();

        float sacc[4][4];
#pragma unroll
        for (int ii = 0; ii < 4; ii++)
#pragma unroll
            for (int jj = 0; jj < 4; jj++) sacc[ii][jj] = 0.f;
#pragma unroll 8
        for (int d = 0; d < 128; d++) {
            float4 a = *(const float4*)&Qt[d * QT_STR + tr * 4];
            float4 b = *(const float4*)&Kt[d * QT_STR + tc * 4];
            float av[4] = {a.x, a.y, a.z, a.w};
            float bv[4] = {b.x, b.y, b.z, b.w};
#pragma unroll
            for (int ii = 0; ii < 4; ii++)
#pragma unroll
                for (int jj = 0; jj < 4; jj++)
                    sacc[ii][jj] = fmaf(av[ii], bv[jj], sacc[ii][jj]);
        }

#pragma unroll
        for (int ii = 0; ii < 4; ii++) {
            const int i = q0 + tr * 4 + ii;
            bool bn[4];
            float rmax = -1e30f;
#pragma unroll
            for (int jj = 0; jj < 4; jj++) {
                int j = j0 + tc * 4 + jj;
                bn[jj] = (j > i) || (i - j > WIN);
                float val = bn[jj] ? -1e30f : sacc[ii][jj];
                sacc[ii][jj] = val;
                rmax = fmaxf(rmax, val);
            }
#pragma unroll
            for (int off = 8; off; off >>= 1)
                rmax = fmaxf(rmax, __shfl_xor_sync(~0u, rmax, off));
            float mnew  = fmaxf(m_i[ii], rmax);
            float alpha = __expf(m_i[ii] - mnew);
            float rsum = 0.f;
#pragma unroll
            for (int jj = 0; jj < 4; jj++) {
                float p = bn[jj] ? 0.f : __expf(sacc[ii][jj] - mnew);
                Ps[(tr * 4 + ii) * PS_STR + tc * 4 + jj] = p;
                rsum += p;
            }
#pragma unroll
            for (int off = 8; off; off >>= 1)
                rsum += __shfl_xor_sync(~0u, rsum, off);
            l_i[ii] = l_i[ii] * alpha + rsum;
            m_i[ii] = mnew;
#pragma unroll
            for (int dd = 0; dd < 8; dd++) o[ii][dd] *= alpha;
        }
        __syncthreads();

#pragma unroll 8
        for (int kk = 0; kk < 64; kk++) {
            float4 v0 = *(const float4*)&Vs[kk * VS_STR + tc * 8];
            float4 v1 = *(const float4*)&Vs[kk * VS_STR + tc * 8 + 4];
#pragma unroll
            for (int ii = 0; ii < 4; ii++) {
                float p = Ps[(tr * 4 + ii) * PS_STR + kk];
                o[ii][0] = fmaf(p, v0.x, o[ii][0]);
                o[ii][1] = fmaf(p, v0.y, o[ii][1]);
                o[ii][2] = fmaf(p, v0.z, o[ii][2]);
                o[ii][3] = fmaf(p, v0.w, o[ii][3]);
                o[ii][4] = fmaf(p, v1.x, o[ii][4]);
                o[ii][5] = fmaf(p, v1.y, o[ii][5]);
                o[ii][6] = fmaf(p, v1.z, o[ii][6]);
                o[ii][7] = fmaf(p, v1.w, o[ii][7]);
            }
        }
    }

#pragma unroll
    for (int ii = 0; ii < 4; ii++) {
        float inv = 1.f / l_i[ii];
        size_t base = (size_t)(q0 + tr * 4 + ii) * EMB + h * HDIM + tc * 8;
        __nv_bfloat16 hh[8], ll[8];
#pragma unroll
        for (int dd = 0; dd < 8; dd++) split1(o[ii][dd] * inv, hh[dd], ll[dd]);
#pragma unroll
        for (int dd = 0; dd < 8; dd += 2) {
            *(__nv_bfloat162*)&ctxh[base + dd] = __nv_bfloat162(hh[dd], hh[dd + 1]);
            *(__nv_bfloat162*)&ctxl[base + dd] = __nv_bfloat162(ll[dd], ll[dd + 1]);
        }
    }
}

// ================= launch =================
extern "C" void kernel_launch(void* const* d_in, const int* in_sizes, int n_in,
                              void* d_out, int out_size)
{
    const float* x    = (const float*)d_in[0];
    const float* Wq   = (const float*)d_in[1];
    const float* bq   = (const float*)d_in[2];
    const float* Wk   = (const float*)d_in[3];
    const float* bk   = (const float*)d_in[4];
    const float* Wv   = (const float*)d_in[5];
    const float* bv   = (const float*)d_in[6];
    const float* Wo   = (const float*)d_in[7];
    const float* bo   = (const float*)d_in[8];
    const float* ln1g = (const float*)d_in[9];
    const float* ln1b = (const float*)d_in[10];
    const float* W1   = (const float*)d_in[11];
    const float* b1   = (const float*)d_in[12];
    const float* W2   = (const float*)d_in[13];
    const float* b2   = (const float*)d_in[14];
    const float* ln2g = (const float*)d_in[15];
    const float* ln2b = (const float*)d_in[16];
    float* out = (float*)d_out;

    float *xn, *qb, *kb, *vb, *x1;
    cudaGetSymbolAddress((void**)&xn,  g_xn);
    cudaGetSymbolAddress((void**)&qb,  g_q);
    cudaGetSymbolAddress((void**)&kb,  g_k);
    cudaGetSymbolAddress((void**)&vb,  g_v);
    cudaGetSymbolAddress((void**)&x1,  g_x1);

    __nv_bfloat16 *xnh, *xnl, *ctxh, *ctxl, *x2h, *x2l, *hh, *hl;
    __nv_bfloat16 *wqh, *wql, *wkh, *wkl, *wvh, *wvl, *woh, *wol, *w1h, *w1l, *w2h, *w2l;
    cudaGetSymbolAddress((void**)&xnh,  g_xn_h);  cudaGetSymbolAddress((void**)&xnl,  g_xn_l);
    cudaGetSymbolAddress((void**)&ctxh, g_ctx_h); cudaGetSymbolAddress((void**)&ctxl, g_ctx_l);
    cudaGetSymbolAddress((void**)&x2h,  g_x2_h);  cudaGetSymbolAddress((void**)&x2l,  g_x2_l);
    cudaGetSymbolAddress((void**)&hh,   g_h_h);   cudaGetSymbolAddress((void**)&hl,   g_h_l);
    cudaGetSymbolAddress((void**)&wqh,  g_WqT_h); cudaGetSymbolAddress((void**)&wql,  g_WqT_l);
    cudaGetSymbolAddress((void**)&wkh,  g_WkT_h); cudaGetSymbolAddress((void**)&wkl,  g_WkT_l);
    cudaGetSymbolAddress((void**)&wvh,  g_WvT_h); cudaGetSymbolAddress((void**)&wvl,  g_WvT_l);
    cudaGetSymbolAddress((void**)&woh,  g_WoT_h); cudaGetSymbolAddress((void**)&wol,  g_WoT_l);
    cudaGetSymbolAddress((void**)&w1h,  g_W1T_h); cudaGetSymbolAddress((void**)&w1l,  g_W1T_l);
    cudaGetSymbolAddress((void**)&w2h,  g_W2T_h); cudaGetSymbolAddress((void**)&w2l,  g_W2T_l);

    cudaFuncSetAttribute(attn_kernel,   cudaFuncAttributeMaxDynamicSharedMemorySize, ATTN_SMEM);
    cudaFuncSetAttribute(gemm_bf16s<0>, cudaFuncAttributeMaxDynamicSharedMemorySize, GEMM_SMEM);
    cudaFuncSetAttribute(gemm_bf16s<1>, cudaFuncAttributeMaxDynamicSharedMemorySize, GEMM_SMEM);
    cudaFuncSetAttribute(gemm_bf16s<2>, cudaFuncAttributeMaxDynamicSharedMemorySize, GEMM_SMEM);

    dim3 gsq(EMB / 128, SLEN / 128);   // 16 x 16
    dim3 gf1(DFF / 128, SLEN / 128);   // 64 x 16
    dim3 tEE(EMB / 32, EMB / 32);
    dim3 tE_F(DFF / 32, EMB / 32);
    dim3 tF_E(EMB / 32, DFF / 32);

    splitT_kernel<<<tEE, 256>>>(Wq, wqh, wql, EMB, EMB);
    splitT_kernel<<<tEE, 256>>>(Wk, wkh, wkl, EMB, EMB);
    splitT_kernel<<<tEE, 256>>>(Wv, wvh, wvl, EMB, EMB);
    splitT_kernel<<<tEE, 256>>>(Wo, woh, wol, EMB, EMB);
    splitT_kernel<<<tE_F, 256>>>(W1, w1h, w1l, EMB, DFF);
    splitT_kernel<<<tF_E, 256>>>(W2, w2h, w2l, DFF, EMB);

    ln_kernel<true><<<SLEN, 256>>>(x, ln1g, ln1b, xn, xnh, xnl);

    gemm_bf16s<0><<<gsq, 256, GEMM_SMEM>>>(xnh, xnl, wqh, wql, bq, nullptr, qb, nullptr, nullptr, SLEN, EMB, EMB);
    gemm_bf16s<0><<<gsq, 256, GEMM_SMEM>>>(xnh, xnl, wkh, wkl, bk, nullptr, kb, nullptr, nullptr, SLEN, EMB, EMB);
    gemm_bf16s<0><<<gsq, 256, GEMM_SMEM>>>(xnh, xnl, wvh, wvl, bv, nullptr, vb, nullptr, nullptr, SLEN, EMB, EMB);

    attn_kernel<<<dim3(SLEN / 64, NHEAD), 256, ATTN_SMEM>>>(qb, kb, vb, ctxh, ctxl);

    gemm_bf16s<1><<<gsq, 256, GEMM_SMEM>>>(ctxh, ctxl, woh, wol, bo, xn, x1, nullptr, nullptr, SLEN, EMB, EMB);

    ln_kernel<false><<<SLEN, 256>>>(x1, ln2g, ln2b, nullptr, x2h, x2l);

    gemm_bf16s<2><<<gf1, 256, GEMM_SMEM>>>(x2h, x2l, w1h, w1l, b1, nullptr, nullptr, hh, hl, SLEN, DFF, EMB);
    gemm_bf16s<1><<<gsq, 256, GEMM_SMEM>>>(hh, hl, w2h, w2l, b2, x1, out, nullptr, nullptr, SLEN, EMB, DFF);
}